// round 7
// baseline (speedup 1.0000x reference)
#include <cuda_runtime.h>
#include <cuda_fp16.h>
#include <math.h>

#define D 64
#define NMAX 100000
#define EMAX 1600000

// Scratch (__device__ globals, allocation-free rule)
__device__ __half2 g_xwp[(size_t)NMAX * 64];   // (xw_low[c], xw_high[c]) per col
__device__ float   g_mlp[(size_t)NMAX * 64];   // relu(x@W_mlp)
__device__ __half2 g_rel[(size_t)NMAX * 64];   // relu'd spmm result, packed (low, high)
__device__ int     g_deg[NMAX];
__device__ int     g_rowstart[NMAX];
__device__ int     g_cursor[NMAX];
__device__ int     g_csrc[EMAX];               // src | (k<<20), dst-grouped
__device__ __half2 g_cv[EMAX];                 // (vl, vh), dst-grouped

// ---------------- CSR build ----------------

__global__ void zero_deg_kernel(int n) {
    int i = blockIdx.x * blockDim.x + threadIdx.x;
    if (i < n) g_deg[i] = 0;
}

__global__ void hist_kernel(const int* __restrict__ dst, int e) {
    int i = blockIdx.x * blockDim.x + threadIdx.x;
    if (i < e) atomicAdd(&g_deg[dst[i]], 1);
}

// One-block exclusive scan over g_deg -> g_rowstart, g_cursor.
__global__ void scan_kernel(int n) {
    __shared__ int ssum[1024];
    int t = threadIdx.x;
    int chunk = (n + 1023) >> 10;
    int lo = t * chunk;
    int hi = min(lo + chunk, n);
    int s = 0;
    for (int i = lo; i < hi; i++) s += g_deg[i];
    ssum[t] = s;
    __syncthreads();
    for (int d = 1; d < 1024; d <<= 1) {
        int v = (t >= d) ? ssum[t - d] : 0;
        __syncthreads();
        ssum[t] += v;
        __syncthreads();
    }
    int off = ssum[t] - s;
    for (int i = lo; i < hi; i++) {
        g_rowstart[i] = off;
        g_cursor[i] = off;
        off += g_deg[i];
    }
}

__global__ void scatter_kernel(const int* __restrict__ src,
                               const int* __restrict__ dst,
                               const int* __restrict__ lab,
                               const float* __restrict__ vl,
                               const float* __restrict__ vh,
                               int e) {
    int i = blockIdx.x * blockDim.x + threadIdx.x;
    if (i >= e) return;
    int s = src[i], d = dst[i];
    int sl = lab[s], dl = lab[d];
    int k = ((sl | dl) < 0) ? 2 : ((sl != dl) ? 1 : 0);
    int pos = atomicAdd(&g_cursor[d], 1);
    g_csrc[pos] = s | (k << 20);
    g_cv[pos] = __floats2half2_rn(vl[i], vh[i]);
}

// ---------------- dense 3-way GEMM ----------------

__global__ void gemm3_kernel(const float* __restrict__ x,
                             const float* __restrict__ wl,
                             const float* __restrict__ wh,
                             const float* __restrict__ wm,
                             int n) {
    __shared__ float sW[3][D][D];
    for (int i = threadIdx.x; i < D * D; i += blockDim.x) {
        sW[0][i >> 6][i & 63] = wl[i];
        sW[1][i >> 6][i & 63] = wh[i];
        sW[2][i >> 6][i & 63] = wm[i];
    }
    __syncthreads();
    int warp = threadIdx.x >> 5, lane = threadIdx.x & 31;
    int row = blockIdx.x * 8 + warp;
    if (row >= n) return;
    float2 xv = *(const float2*)(x + (size_t)row * D + lane * 2);
    float a0 = 0.f, a1 = 0.f, b0 = 0.f, b1 = 0.f, c0 = 0.f, c1 = 0.f;
#pragma unroll
    for (int k = 0; k < D; k++) {
        float xk = __shfl_sync(0xffffffffu, (k & 1) ? xv.y : xv.x, k >> 1);
        a0 += xk * sW[0][k][lane];      a1 += xk * sW[0][k][lane + 32];
        b0 += xk * sW[1][k][lane];      b1 += xk * sW[1][k][lane + 32];
        c0 += xk * sW[2][k][lane];      c1 += xk * sW[2][k][lane + 32];
    }
    size_t o = (size_t)row * 64;
    g_xwp[o + lane]      = __floats2half2_rn(a0, b0);
    g_xwp[o + lane + 32] = __floats2half2_rn(a1, b1);
    g_mlp[o + lane] = fmaxf(c0, 0.f);
    g_mlp[o + lane + 32] = fmaxf(c1, 0.f);
}

// pass1: dst-grouped gather SpMM. 16 threads/node, fp32 accum, relu'd fp16 write.
__global__ void spmm_gather_kernel(int n) {
    int t = blockIdx.x * blockDim.x + threadIdx.x;
    int node = t >> 4;
    if (node >= n) return;
    int c4 = t & 15;
    int start = g_rowstart[node];
    int deg = g_deg[node];
    const float4* base = (const float4*)g_xwp;
    float2 a0 = make_float2(0.f, 0.f), a1 = a0, a2 = a0, a3 = a0;
#pragma unroll 2
    for (int i = 0; i < deg; i++) {
        int sw = g_csrc[start + i];
        float2 vv = __half22float2(g_cv[start + i]);
        int s = sw & 0xFFFFF;
        float4 raw = base[(size_t)s * 16 + c4];
        float2 f0 = __half22float2(((__half2*)&raw)[0]);
        float2 f1 = __half22float2(((__half2*)&raw)[1]);
        float2 f2 = __half22float2(((__half2*)&raw)[2]);
        float2 f3 = __half22float2(((__half2*)&raw)[3]);
        a0.x += vv.x * f0.x; a0.y += vv.y * f0.y;
        a1.x += vv.x * f1.x; a1.y += vv.y * f1.y;
        a2.x += vv.x * f2.x; a2.y += vv.y * f2.y;
        a3.x += vv.x * f3.x; a3.y += vv.y * f3.y;
    }
    float4 pk;
    ((__half2*)&pk)[0] = __floats2half2_rn(fmaxf(a0.x, 0.f), fmaxf(a0.y, 0.f));
    ((__half2*)&pk)[1] = __floats2half2_rn(fmaxf(a1.x, 0.f), fmaxf(a1.y, 0.f));
    ((__half2*)&pk)[2] = __floats2half2_rn(fmaxf(a2.x, 0.f), fmaxf(a2.y, 0.f));
    ((__half2*)&pk)[3] = __floats2half2_rn(fmaxf(a3.x, 0.f), fmaxf(a3.y, 0.f));
    ((float4*)g_rel)[(size_t)node * 16 + c4] = pk;
}

// pass2 fused with epilogue: bucket sums in registers, logits via width-16 shuffles,
// softmax, combine, single float4 store. 16 threads/node.
__global__ void agg_final_kernel(const float* __restrict__ alf, const float* __restrict__ ahf,
                                 const float* __restrict__ alb, const float* __restrict__ ahb,
                                 const float* __restrict__ alu, const float* __restrict__ ahu,
                                 const float* __restrict__ am,  const float* __restrict__ a7,
                                 float* __restrict__ out, int n) {
    __shared__ float sV[7][D];   // slot order: alf,ahf,alb,ahb,alu,ahu,am
    __shared__ float sA7[49];
    if (threadIdx.x < D) {
        int c = threadIdx.x;
        sV[0][c] = alf[c]; sV[1][c] = ahf[c]; sV[2][c] = alb[c];
        sV[3][c] = ahb[c]; sV[4][c] = alu[c]; sV[5][c] = ahu[c];
        sV[6][c] = am[c];
    }
    if (threadIdx.x < 49) sA7[threadIdx.x] = a7[threadIdx.x];
    __syncthreads();
    int t = blockIdx.x * blockDim.x + threadIdx.x;
    int node = t >> 4;
    if (node >= n) return;
    int c4 = t & 15;
    int start = g_rowstart[node];
    int deg = g_deg[node];
    const float4* base = (const float4*)g_rel;

    __half2 ho0, ho1, ho2, ho3, he0, he1, he2, he3, un0, un1, un2, un3;
    __half2 z = __float2half2_rn(0.f);
    ho0 = ho1 = ho2 = ho3 = z;
    he0 = he1 = he2 = he3 = z;
    un0 = un1 = un2 = un3 = z;
#pragma unroll 2
    for (int i = 0; i < deg; i++) {
        int sw = g_csrc[start + i];
        int s = sw & 0xFFFFF;
        int k = sw >> 20;
        float4 raw = base[(size_t)s * 16 + c4];
        __half2 h0 = ((__half2*)&raw)[0];
        __half2 h1 = ((__half2*)&raw)[1];
        __half2 h2 = ((__half2*)&raw)[2];
        __half2 h3 = ((__half2*)&raw)[3];
        if (k == 0) {
            ho0 = __hadd2(ho0, h0); ho1 = __hadd2(ho1, h1);
            ho2 = __hadd2(ho2, h2); ho3 = __hadd2(ho3, h3);
        } else if (k == 1) {
            he0 = __hadd2(he0, h0); he1 = __hadd2(he1, h1);
            he2 = __hadd2(he2, h2); he3 = __hadd2(he3, h3);
        } else {
            un0 = __hadd2(un0, h0); un1 = __hadd2(un1, h1);
            un2 = __hadd2(un2, h2); un3 = __hadd2(un3, h3);
        }
    }

    int c = c4 * 4;
    float4 m4 = ((const float4*)g_mlp)[(size_t)node * 16 + c4];
    const float* mp = (const float*)&m4;

    float ps[7] = {0.f, 0.f, 0.f, 0.f, 0.f, 0.f, 0.f};
    {
        __half2 he[4] = {he0, he1, he2, he3};
        __half2 ho[4] = {ho0, ho1, ho2, ho3};
        __half2 un[4] = {un0, un1, un2, un3};
#pragma unroll
        for (int j = 0; j < 4; j++) {
            float2 hef = __half22float2(he[j]);
            float2 hof = __half22float2(ho[j]);
            float2 unf = __half22float2(un[j]);
            ps[0] += hef.x * sV[0][c + j];
            ps[1] += hef.y * sV[1][c + j];
            ps[2] += hof.x * sV[2][c + j];
            ps[3] += hof.y * sV[3][c + j];
            ps[4] += unf.x * sV[4][c + j];
            ps[5] += unf.y * sV[5][c + j];
            ps[6] += mp[j] * sV[6][c + j];
        }
    }
#pragma unroll
    for (int off = 8; off; off >>= 1)
#pragma unroll
        for (int j = 0; j < 7; j++)
            ps[j] += __shfl_xor_sync(0xffffffffu, ps[j], off, 16);

    float f[7];
#pragma unroll
    for (int j = 0; j < 7; j++)
        f[j] = 1.f / (1.f + __expf(-ps[j]));
    float lg[7];
    float m = -1e30f;
#pragma unroll
    for (int i = 0; i < 7; i++) {
        float s = 0.f;
#pragma unroll
        for (int j = 0; j < 7; j++) s += f[j] * sA7[j * 7 + i];
        lg[i] = s * (1.0f / 7.0f);
        m = fmaxf(m, lg[i]);
    }
    float sum = 0.f;
#pragma unroll
    for (int i = 0; i < 7; i++) { lg[i] = __expf(lg[i] - m); sum += lg[i]; }
    float inv = 7.0f / sum;
#pragma unroll
    for (int i = 0; i < 7; i++) lg[i] *= inv;

    float4 r;
    {
        __half2 he[4] = {he0, he1, he2, he3};
        __half2 ho[4] = {ho0, ho1, ho2, ho3};
        __half2 un[4] = {un0, un1, un2, un3};
        float* rp = (float*)&r;
#pragma unroll
        for (int j = 0; j < 4; j++) {
            float2 hef = __half22float2(he[j]);
            float2 hof = __half22float2(ho[j]);
            float2 unf = __half22float2(un[j]);
            rp[j] = lg[0] * hef.x + lg[1] * hef.y + lg[2] * hof.x + lg[3] * hof.y
                  + lg[4] * unf.x + lg[5] * unf.y + lg[6] * mp[j];
        }
    }
    ((float4*)out)[(size_t)node * 16 + c4] = r;
}

extern "C" void kernel_launch(void* const* d_in, const int* in_sizes, int n_in,
                              void* d_out, int out_size) {
    const float* x   = (const float*)d_in[0];
    const float* vl  = (const float*)d_in[1];
    const float* vh  = (const float*)d_in[2];
    const float* wl  = (const float*)d_in[3];
    const float* wh  = (const float*)d_in[4];
    const float* wm  = (const float*)d_in[5];
    const float* alf = (const float*)d_in[6];
    const float* ahf = (const float*)d_in[7];
    const float* alb = (const float*)d_in[8];
    const float* ahb = (const float*)d_in[9];
    const float* alu = (const float*)d_in[10];
    const float* ahu = (const float*)d_in[11];
    const float* am  = (const float*)d_in[12];
    const float* a7  = (const float*)d_in[13];
    const int* src   = (const int*)d_in[14];
    const int* dst   = (const int*)d_in[15];
    const int* lab   = (const int*)d_in[16];
    int n = in_sizes[0] / D;
    int e = in_sizes[14];
    float* out = (float*)d_out;

    zero_deg_kernel<<<(n + 255) / 256, 256>>>(n);
    hist_kernel<<<(e + 255) / 256, 256>>>(dst, e);
    scan_kernel<<<1, 1024>>>(n);
    scatter_kernel<<<(e + 255) / 256, 256>>>(src, dst, lab, vl, vh, e);
    gemm3_kernel<<<(n + 7) / 8, 256>>>(x, wl, wh, wm, n);
    int nt = n * 16;
    spmm_gather_kernel<<<(nt + 255) / 256, 256>>>(n);
    agg_final_kernel<<<(nt + 255) / 256, 256>>>(alf, ahf, alb, ahb, alu, ahu, am, a7, out, n);
}